// round 2
// baseline (speedup 1.0000x reference)
#include <cuda_runtime.h>
#include <cuda_bf16.h>

#define L_RES 512
#define C_S   256
#define C_Z   128
#define LN_EPS 1e-5f

// Scratch (no allocations allowed)
__device__ float g_u[L_RES * C_S];     // LayerNorm'd embeddings (512KB)
__device__ float g_zjb[L_RES * C_Z];   // u @ W2 + b_pair        (256KB)

// ---------------------------------------------------------------------------
// Kernel 1: gather + LayerNorm + zjb = u @ W2 + b_pair. One block per residue.
// ---------------------------------------------------------------------------
__global__ void prep_kernel(const int* __restrict__ seq,
                            const int* __restrict__ chain,
                            const int* __restrict__ ridx,
                            const float* __restrict__ E_aa,
                            const float* __restrict__ E_pos,
                            const float* __restrict__ E_chain,
                            const float* __restrict__ W_pair,
                            const float* __restrict__ b_pair,
                            const float* __restrict__ ln_w,
                            const float* __restrict__ ln_b,
                            float* __restrict__ out_s)
{
    int i = blockIdx.x;
    int t = threadIdx.x;            // 256 threads == C_S

    __shared__ float u_s[C_S];
    __shared__ float red[8];
    __shared__ float mu_sh, rstd_sh;

    int sq = seq[i], ci = chain[i], ri = ridx[i];
    float v = E_aa[sq * C_S + t] + E_pos[ri * C_S + t] + E_chain[ci * C_S + t];
    out_s[i * C_S + t] = v;

    // mean
    float x = v;
    #pragma unroll
    for (int o = 16; o; o >>= 1) x += __shfl_xor_sync(0xffffffffu, x, o);
    if ((t & 31) == 0) red[t >> 5] = x;
    __syncthreads();
    if (t == 0) {
        float s = 0.f;
        #pragma unroll
        for (int w = 0; w < 8; w++) s += red[w];
        mu_sh = s * (1.f / C_S);
    }
    __syncthreads();
    float mu = mu_sh;
    float d  = v - mu;

    // var
    x = d * d;
    #pragma unroll
    for (int o = 16; o; o >>= 1) x += __shfl_xor_sync(0xffffffffu, x, o);
    if ((t & 31) == 0) red[t >> 5] = x;
    __syncthreads();
    if (t == 0) {
        float s = 0.f;
        #pragma unroll
        for (int w = 0; w < 8; w++) s += red[w];
        rstd_sh = rsqrtf(s * (1.f / C_S) + LN_EPS);
    }
    __syncthreads();

    float uu = d * rstd_sh * ln_w[t] + ln_b[t];
    g_u[i * C_S + t] = uu;
    u_s[t] = uu;
    __syncthreads();

    // zjb[i, z] = sum_c u[i,c] * W2[c,z] + b_pair[z]   (W2 = rows [C_S, 2*C_S))
    if (t < C_Z) {
        float acc = b_pair[t];
        #pragma unroll 8
        for (int c = 0; c < C_S; c++)
            acc += u_s[c] * W_pair[(C_S + c) * C_Z + t];
        g_zjb[i * C_Z + t] = acc;
    }
}

// ---------------------------------------------------------------------------
// Kernel 2: per (i-tile of 128, j): D[128,128] = U_tile[128,256] @ B[256,128]
// where B[c,z] = u[j,c]*W3[c,z] + W1[c,z]   (folds zi into the GEMM).
// Epilogue adds zjb[j,:] + E_chainpair + E_relpos and stores z.
// All FMA work as packed fma.rn.f32x2 (needed to hit 128 FMA/cyc/SM).
// ---------------------------------------------------------------------------
#define BM 128
#define BN 128
#define BK 32

__global__ __launch_bounds__(256, 2)
void pair_kernel(const int* __restrict__ chain,
                 const int* __restrict__ ridx,
                 const float* __restrict__ E_cp,   // (4,   C_Z)
                 const float* __restrict__ E_rp,   // (66,  C_Z)
                 const float* __restrict__ W_pair, // (768, C_Z)
                 float* __restrict__ out_z)        // (L, L, C_Z)
{
    __shared__ float As[BK][BM];      // transposed: As[c][i]
    __shared__ float Bs[BK][BN];      // Bs[c][z]
    __shared__ int   chain_s[BM];
    __shared__ int   ridx_s[BM];
    __shared__ float zjb_s[C_Z];

    const int t  = threadIdx.x;       // 256 threads
    const int j  = blockIdx.x;        // 0..511
    const int i0 = blockIdx.y * BM;   // 0,128,256,384

    if (t < BM) {
        chain_s[t] = chain[i0 + t];
        ridx_s[t]  = ridx[i0 + t];
    }
    if (t < C_Z) zjb_s[t] = g_zjb[j * C_Z + t];

    const int cj = chain[j];
    const int rj = ridx[j];

    const int tx = t & 15;            // z-tile:  columns tx*8 .. tx*8+7
    const int ty = t >> 4;            // i-tile:  rows    ty*8 .. ty*8+7

    unsigned long long acc[8][4];     // 8 rows x 4 f32x2 z-pairs
    #pragma unroll
    for (int r = 0; r < 8; r++)
        #pragma unroll
        for (int p = 0; p < 4; p++) acc[r][p] = 0ull;

    const int arow = t >> 1;              // A load: row, then 16 cols
    const int acb  = (t & 1) * 16;
    const int bk   = t >> 3;              // B build: c index within chunk
    const int bzb  = (t & 7) * 16;        // 16 consecutive z

    for (int kc = 0; kc < C_S; kc += BK) {
        // ---- load A chunk (coalesced), store transposed ----
        const float4* gA = (const float4*)(g_u + (size_t)(i0 + arow) * C_S + kc + acb);
        #pragma unroll
        for (int q = 0; q < 4; q++) {
            float4 v = gA[q];
            int c = acb + q * 4;
            As[c + 0][arow] = v.x;
            As[c + 1][arow] = v.y;
            As[c + 2][arow] = v.z;
            As[c + 3][arow] = v.w;
        }
        // ---- build B chunk: B[c,z] = u[j,c]*W3[c,z] + W1[c,z] ----
        {
            int c = kc + bk;
            float ujc = g_u[j * C_S + c];
            const float4* w3 = (const float4*)(W_pair + (size_t)(2 * C_S + c) * C_Z + bzb);
            const float4* w1 = (const float4*)(W_pair + (size_t)c * C_Z + bzb);
            #pragma unroll
            for (int q = 0; q < 4; q++) {
                float4 a = w3[q], b = w1[q];
                float4 o;
                o.x = fmaf(ujc, a.x, b.x);
                o.y = fmaf(ujc, a.y, b.y);
                o.z = fmaf(ujc, a.z, b.z);
                o.w = fmaf(ujc, a.w, b.w);
                *(float4*)&Bs[bk][bzb + q * 4] = o;
            }
        }
        __syncthreads();

        #pragma unroll 8
        for (int k = 0; k < BK; k++) {
            float a[8];
            *(float4*)(a + 0) = *(const float4*)&As[k][ty * 8];
            *(float4*)(a + 4) = *(const float4*)&As[k][ty * 8 + 4];
            unsigned long long b[4];
            const unsigned long long* pb =
                (const unsigned long long*)&Bs[k][tx * 8];
            b[0] = pb[0]; b[1] = pb[1]; b[2] = pb[2]; b[3] = pb[3];
            #pragma unroll
            for (int r = 0; r < 8; r++) {
                unsigned long long ap;
                asm("mov.b64 %0, {%1, %2};" : "=l"(ap) : "f"(a[r]), "f"(a[r]));
                #pragma unroll
                for (int p = 0; p < 4; p++)
                    asm("fma.rn.f32x2 %0, %1, %2, %0;"
                        : "+l"(acc[r][p]) : "l"(ap), "l"(b[p]));
            }
        }
        __syncthreads();
    }

    // ---- epilogue ----
    float zb[8];
    *(float4*)(zb + 0) = *(const float4*)&zjb_s[tx * 8];
    *(float4*)(zb + 4) = *(const float4*)&zjb_s[tx * 8 + 4];

    #pragma unroll
    for (int r = 0; r < 8; r++) {
        int il = ty * 8 + r;
        int irow = i0 + il;
        int ci = chain_s[il], ri = ridx_s[il];
        int cp = ci * 2 + cj;
        int dd = ri - rj;
        int dcl = dd < -32 ? -32 : (dd > 32 ? 32 : dd);
        int rp = (ci == cj) ? (dcl + 32) : 65;

        const float4* ecp = (const float4*)(E_cp + (size_t)cp * C_Z + tx * 8);
        const float4* erp = (const float4*)(E_rp + (size_t)rp * C_Z + tx * 8);
        float4 e0 = ecp[0], e1 = ecp[1];
        float4 p0 = erp[0], p1 = erp[1];

        float lo, hi;
        float4 o0, o1;
        asm("mov.b64 {%0, %1}, %2;" : "=f"(lo), "=f"(hi) : "l"(acc[r][0]));
        o0.x = lo + zb[0] + e0.x + p0.x;
        o0.y = hi + zb[1] + e0.y + p0.y;
        asm("mov.b64 {%0, %1}, %2;" : "=f"(lo), "=f"(hi) : "l"(acc[r][1]));
        o0.z = lo + zb[2] + e0.z + p0.z;
        o0.w = hi + zb[3] + e0.w + p0.w;
        asm("mov.b64 {%0, %1}, %2;" : "=f"(lo), "=f"(hi) : "l"(acc[r][2]));
        o1.x = lo + zb[4] + e1.x + p1.x;
        o1.y = hi + zb[5] + e1.y + p1.y;
        asm("mov.b64 {%0, %1}, %2;" : "=f"(lo), "=f"(hi) : "l"(acc[r][3]));
        o1.z = lo + zb[6] + e1.z + p1.z;
        o1.w = hi + zb[7] + e1.w + p1.w;

        float* outp = out_z + ((size_t)irow * L_RES + j) * C_Z + tx * 8;
        *(float4*)(outp + 0) = o0;
        *(float4*)(outp + 4) = o1;
    }
}

// ---------------------------------------------------------------------------
extern "C" void kernel_launch(void* const* d_in, const int* in_sizes, int n_in,
                              void* d_out, int out_size)
{
    const int*   seq     = (const int*)  d_in[0];
    const int*   chain   = (const int*)  d_in[1];
    const int*   ridx    = (const int*)  d_in[2];
    const float* E_aa    = (const float*)d_in[3];
    const float* E_pos   = (const float*)d_in[4];
    const float* E_chain = (const float*)d_in[5];
    const float* E_cp    = (const float*)d_in[6];
    const float* E_rp    = (const float*)d_in[7];
    const float* W_pair  = (const float*)d_in[8];
    const float* b_pair  = (const float*)d_in[9];
    const float* ln_w    = (const float*)d_in[10];
    const float* ln_b    = (const float*)d_in[11];

    float* out_s = (float*)d_out;
    float* out_z = out_s + (size_t)L_RES * C_S;

    prep_kernel<<<L_RES, C_S>>>(seq, chain, ridx, E_aa, E_pos, E_chain,
                                W_pair, b_pair, ln_w, ln_b, out_s);
    pair_kernel<<<dim3(L_RES, L_RES / BM), 256>>>(chain, ridx, E_cp, E_rp,
                                                  W_pair, out_z);
}

// round 3
// speedup vs baseline: 1.0005x; 1.0005x over previous
#include <cuda_runtime.h>
#include <cuda_bf16.h>

#define L_RES 512
#define C_S   256
#define C_Z   128
#define LN_EPS 1e-5f

// Scratch (no allocations allowed)
__device__ float g_u[L_RES * C_S];     // LayerNorm'd embeddings (512KB)
__device__ float g_zjb[L_RES * C_Z];   // u @ W2 + b_pair        (256KB)

// ---------------------------------------------------------------------------
// Kernel 1: gather + LayerNorm + zjb = u @ W2 + b_pair. One block per residue.
// ---------------------------------------------------------------------------
__global__ void prep_kernel(const int* __restrict__ seq,
                            const int* __restrict__ chain,
                            const int* __restrict__ ridx,
                            const float* __restrict__ E_aa,
                            const float* __restrict__ E_pos,
                            const float* __restrict__ E_chain,
                            const float* __restrict__ W_pair,
                            const float* __restrict__ b_pair,
                            const float* __restrict__ ln_w,
                            const float* __restrict__ ln_b,
                            float* __restrict__ out_s)
{
    int i = blockIdx.x;
    int t = threadIdx.x;            // 256 threads == C_S

    __shared__ float u_s[C_S];
    __shared__ float red[8];
    __shared__ float mu_sh, rstd_sh;

    int sq = seq[i], ci = chain[i], ri = ridx[i];
    float v = E_aa[sq * C_S + t] + E_pos[ri * C_S + t] + E_chain[ci * C_S + t];
    out_s[i * C_S + t] = v;

    // mean
    float x = v;
    #pragma unroll
    for (int o = 16; o; o >>= 1) x += __shfl_xor_sync(0xffffffffu, x, o);
    if ((t & 31) == 0) red[t >> 5] = x;
    __syncthreads();
    if (t == 0) {
        float s = 0.f;
        #pragma unroll
        for (int w = 0; w < 8; w++) s += red[w];
        mu_sh = s * (1.f / C_S);
    }
    __syncthreads();
    float mu = mu_sh;
    float d  = v - mu;

    // var
    x = d * d;
    #pragma unroll
    for (int o = 16; o; o >>= 1) x += __shfl_xor_sync(0xffffffffu, x, o);
    if ((t & 31) == 0) red[t >> 5] = x;
    __syncthreads();
    if (t == 0) {
        float s = 0.f;
        #pragma unroll
        for (int w = 0; w < 8; w++) s += red[w];
        rstd_sh = rsqrtf(s * (1.f / C_S) + LN_EPS);
    }
    __syncthreads();

    float uu = d * rstd_sh * ln_w[t] + ln_b[t];
    g_u[i * C_S + t] = uu;
    u_s[t] = uu;
    __syncthreads();

    // zjb[i, z] = sum_c u[i,c] * W2[c,z] + b_pair[z]   (W2 = rows [C_S, 2*C_S))
    if (t < C_Z) {
        float acc = b_pair[t];
        #pragma unroll 8
        for (int c = 0; c < C_S; c++)
            acc += u_s[c] * W_pair[(C_S + c) * C_Z + t];
        g_zjb[i * C_Z + t] = acc;
    }
}

// ---------------------------------------------------------------------------
// Kernel 2: per (i-tile of 128, j): D[128,128] = U_tile[128,256] @ B[256,128]
// where B[c,z] = u[j,c]*W3[c,z] + W1[c,z]   (folds zi into the GEMM).
// Epilogue adds zjb[j,:] + E_chainpair + E_relpos and stores z.
// All FMA work as packed fma.rn.f32x2 (needed to hit 128 FMA/cyc/SM).
// ---------------------------------------------------------------------------
#define BM 128
#define BN 128
#define BK 32

__global__ __launch_bounds__(256, 2)
void pair_kernel(const int* __restrict__ chain,
                 const int* __restrict__ ridx,
                 const float* __restrict__ E_cp,   // (4,   C_Z)
                 const float* __restrict__ E_rp,   // (66,  C_Z)
                 const float* __restrict__ W_pair, // (768, C_Z)
                 float* __restrict__ out_z)        // (L, L, C_Z)
{
    __shared__ float As[BK][BM];      // transposed: As[c][i]
    __shared__ float Bs[BK][BN];      // Bs[c][z]
    __shared__ int   chain_s[BM];
    __shared__ int   ridx_s[BM];
    __shared__ float zjb_s[C_Z];

    const int t  = threadIdx.x;       // 256 threads
    const int j  = blockIdx.x;        // 0..511
    const int i0 = blockIdx.y * BM;   // 0,128,256,384

    if (t < BM) {
        chain_s[t] = chain[i0 + t];
        ridx_s[t]  = ridx[i0 + t];
    }
    if (t < C_Z) zjb_s[t] = g_zjb[j * C_Z + t];

    const int cj = chain[j];
    const int rj = ridx[j];

    const int tx = t & 15;            // z-tile:  columns tx*8 .. tx*8+7
    const int ty = t >> 4;            // i-tile:  rows    ty*8 .. ty*8+7

    unsigned long long acc[8][4];     // 8 rows x 4 f32x2 z-pairs
    #pragma unroll
    for (int r = 0; r < 8; r++)
        #pragma unroll
        for (int p = 0; p < 4; p++) acc[r][p] = 0ull;

    const int arow = t >> 1;              // A load: row, then 16 cols
    const int acb  = (t & 1) * 16;
    const int bk   = t >> 3;              // B build: c index within chunk
    const int bzb  = (t & 7) * 16;        // 16 consecutive z

    for (int kc = 0; kc < C_S; kc += BK) {
        // ---- load A chunk (coalesced), store transposed ----
        const float4* gA = (const float4*)(g_u + (size_t)(i0 + arow) * C_S + kc + acb);
        #pragma unroll
        for (int q = 0; q < 4; q++) {
            float4 v = gA[q];
            int c = acb + q * 4;
            As[c + 0][arow] = v.x;
            As[c + 1][arow] = v.y;
            As[c + 2][arow] = v.z;
            As[c + 3][arow] = v.w;
        }
        // ---- build B chunk: B[c,z] = u[j,c]*W3[c,z] + W1[c,z] ----
        {
            int c = kc + bk;
            float ujc = g_u[j * C_S + c];
            const float4* w3 = (const float4*)(W_pair + (size_t)(2 * C_S + c) * C_Z + bzb);
            const float4* w1 = (const float4*)(W_pair + (size_t)c * C_Z + bzb);
            #pragma unroll
            for (int q = 0; q < 4; q++) {
                float4 a = w3[q], b = w1[q];
                float4 o;
                o.x = fmaf(ujc, a.x, b.x);
                o.y = fmaf(ujc, a.y, b.y);
                o.z = fmaf(ujc, a.z, b.z);
                o.w = fmaf(ujc, a.w, b.w);
                *(float4*)&Bs[bk][bzb + q * 4] = o;
            }
        }
        __syncthreads();

        #pragma unroll 8
        for (int k = 0; k < BK; k++) {
            float a[8];
            *(float4*)(a + 0) = *(const float4*)&As[k][ty * 8];
            *(float4*)(a + 4) = *(const float4*)&As[k][ty * 8 + 4];
            unsigned long long b[4];
            const unsigned long long* pb =
                (const unsigned long long*)&Bs[k][tx * 8];
            b[0] = pb[0]; b[1] = pb[1]; b[2] = pb[2]; b[3] = pb[3];
            #pragma unroll
            for (int r = 0; r < 8; r++) {
                unsigned long long ap;
                asm("mov.b64 %0, {%1, %2};" : "=l"(ap) : "f"(a[r]), "f"(a[r]));
                #pragma unroll
                for (int p = 0; p < 4; p++)
                    asm("fma.rn.f32x2 %0, %1, %2, %0;"
                        : "+l"(acc[r][p]) : "l"(ap), "l"(b[p]));
            }
        }
        __syncthreads();
    }

    // ---- epilogue ----
    float zb[8];
    *(float4*)(zb + 0) = *(const float4*)&zjb_s[tx * 8];
    *(float4*)(zb + 4) = *(const float4*)&zjb_s[tx * 8 + 4];

    #pragma unroll
    for (int r = 0; r < 8; r++) {
        int il = ty * 8 + r;
        int irow = i0 + il;
        int ci = chain_s[il], ri = ridx_s[il];
        int cp = ci * 2 + cj;
        int dd = ri - rj;
        int dcl = dd < -32 ? -32 : (dd > 32 ? 32 : dd);
        int rp = (ci == cj) ? (dcl + 32) : 65;

        const float4* ecp = (const float4*)(E_cp + (size_t)cp * C_Z + tx * 8);
        const float4* erp = (const float4*)(E_rp + (size_t)rp * C_Z + tx * 8);
        float4 e0 = ecp[0], e1 = ecp[1];
        float4 p0 = erp[0], p1 = erp[1];

        float lo, hi;
        float4 o0, o1;
        asm("mov.b64 {%0, %1}, %2;" : "=f"(lo), "=f"(hi) : "l"(acc[r][0]));
        o0.x = lo + zb[0] + e0.x + p0.x;
        o0.y = hi + zb[1] + e0.y + p0.y;
        asm("mov.b64 {%0, %1}, %2;" : "=f"(lo), "=f"(hi) : "l"(acc[r][1]));
        o0.z = lo + zb[2] + e0.z + p0.z;
        o0.w = hi + zb[3] + e0.w + p0.w;
        asm("mov.b64 {%0, %1}, %2;" : "=f"(lo), "=f"(hi) : "l"(acc[r][2]));
        o1.x = lo + zb[4] + e1.x + p1.x;
        o1.y = hi + zb[5] + e1.y + p1.y;
        asm("mov.b64 {%0, %1}, %2;" : "=f"(lo), "=f"(hi) : "l"(acc[r][3]));
        o1.z = lo + zb[6] + e1.z + p1.z;
        o1.w = hi + zb[7] + e1.w + p1.w;

        float* outp = out_z + ((size_t)irow * L_RES + j) * C_Z + tx * 8;
        *(float4*)(outp + 0) = o0;
        *(float4*)(outp + 4) = o1;
    }
}

// ---------------------------------------------------------------------------
extern "C" void kernel_launch(void* const* d_in, const int* in_sizes, int n_in,
                              void* d_out, int out_size)
{
    const int*   seq     = (const int*)  d_in[0];
    const int*   chain   = (const int*)  d_in[1];
    const int*   ridx    = (const int*)  d_in[2];
    const float* E_aa    = (const float*)d_in[3];
    const float* E_pos   = (const float*)d_in[4];
    const float* E_chain = (const float*)d_in[5];
    const float* E_cp    = (const float*)d_in[6];
    const float* E_rp    = (const float*)d_in[7];
    const float* W_pair  = (const float*)d_in[8];
    const float* b_pair  = (const float*)d_in[9];
    const float* ln_w    = (const float*)d_in[10];
    const float* ln_b    = (const float*)d_in[11];

    float* out_s = (float*)d_out;
    float* out_z = out_s + (size_t)L_RES * C_S;

    prep_kernel<<<L_RES, C_S>>>(seq, chain, ridx, E_aa, E_pos, E_chain,
                                W_pair, b_pair, ln_w, ln_b, out_s);
    pair_kernel<<<dim3(L_RES, L_RES / BM), 256>>>(chain, ridx, E_cp, E_rp,
                                                  W_pair, out_z);
}

// round 5
// speedup vs baseline: 1.4457x; 1.4450x over previous
#include <cuda_runtime.h>
#include <cuda_bf16.h>
#include <cstdint>

#define L_RES 512
#define C_S   256
#define C_Z   128
#define LN_EPS 1e-5f

// ---------------------------------------------------------------------------
// Device scratch
// ---------------------------------------------------------------------------
__device__ __align__(16) float g_u[L_RES * C_S];            // LayerNorm'd embeddings
__device__ __align__(16) float g_zjb[L_RES * C_Z];          // u @ W2 + b_pair
__device__ __align__(16) float g_zib[L_RES * C_Z];          // u @ W1
__device__ __align__(16) __nv_bfloat16 g_w3t_hi[C_Z * C_S]; // W3^T hi  [z][c]
__device__ __align__(16) __nv_bfloat16 g_w3t_lo[C_Z * C_S]; // W3^T lo  [z][c]

// ---------------------------------------------------------------------------
// Base-PTX tensor helpers (valid on compute_103: no 'a'-features)
// ---------------------------------------------------------------------------
__device__ __forceinline__ uint32_t smem_u32(const void* p) {
    uint32_t a;
    asm("{ .reg .u64 t; cvta.to.shared.u64 t, %1; cvt.u32.u64 %0, t; }"
        : "=r"(a) : "l"(p));
    return a;
}

__device__ __forceinline__ void ldsm_x4(uint32_t& r0, uint32_t& r1,
                                        uint32_t& r2, uint32_t& r3, uint32_t addr) {
    asm volatile("ldmatrix.sync.aligned.m8n8.x4.shared.b16 {%0,%1,%2,%3}, [%4];"
                 : "=r"(r0), "=r"(r1), "=r"(r2), "=r"(r3) : "r"(addr));
}

__device__ __forceinline__ void mma16816(float* c, const uint32_t* a, const uint32_t* b) {
    asm volatile(
        "mma.sync.aligned.m16n8k16.row.col.f32.bf16.bf16.f32 "
        "{%0,%1,%2,%3}, {%4,%5,%6,%7}, {%8,%9}, {%0,%1,%2,%3};"
        : "+f"(c[0]), "+f"(c[1]), "+f"(c[2]), "+f"(c[3])
        : "r"(a[0]), "r"(a[1]), "r"(a[2]), "r"(a[3]), "r"(b[0]), "r"(b[1]));
}

__device__ __forceinline__ uint32_t pack_bf16x2(float hi_lane, float lo_lane) {
    uint32_t d;
    asm("cvt.rn.bf16x2.f32 %0, %1, %2;" : "=r"(d) : "f"(hi_lane), "f"(lo_lane));
    return d;
}

// ---------------------------------------------------------------------------
// Kernel 1: gather + LayerNorm + zjb (u@W2 + b) + zib (u@W1)
// ---------------------------------------------------------------------------
__global__ void prep_kernel(const int* __restrict__ seq,
                            const int* __restrict__ chain,
                            const int* __restrict__ ridx,
                            const float* __restrict__ E_aa,
                            const float* __restrict__ E_pos,
                            const float* __restrict__ E_chain,
                            const float* __restrict__ W_pair,
                            const float* __restrict__ b_pair,
                            const float* __restrict__ ln_w,
                            const float* __restrict__ ln_b,
                            float* __restrict__ out_s)
{
    int i = blockIdx.x;
    int t = threadIdx.x;            // 256 threads == C_S

    __shared__ float u_s[C_S];
    __shared__ float red[8];
    __shared__ float mu_sh, rstd_sh;

    int sq = seq[i], ci = chain[i], ri = ridx[i];
    float v = E_aa[sq * C_S + t] + E_pos[ri * C_S + t] + E_chain[ci * C_S + t];
    out_s[i * C_S + t] = v;

    float x = v;
    #pragma unroll
    for (int o = 16; o; o >>= 1) x += __shfl_xor_sync(0xffffffffu, x, o);
    if ((t & 31) == 0) red[t >> 5] = x;
    __syncthreads();
    if (t == 0) {
        float s = 0.f;
        #pragma unroll
        for (int w = 0; w < 8; w++) s += red[w];
        mu_sh = s * (1.f / C_S);
    }
    __syncthreads();
    float mu = mu_sh;
    float d  = v - mu;

    x = d * d;
    #pragma unroll
    for (int o = 16; o; o >>= 1) x += __shfl_xor_sync(0xffffffffu, x, o);
    if ((t & 31) == 0) red[t >> 5] = x;
    __syncthreads();
    if (t == 0) {
        float s = 0.f;
        #pragma unroll
        for (int w = 0; w < 8; w++) s += red[w];
        rstd_sh = rsqrtf(s * (1.f / C_S) + LN_EPS);
    }
    __syncthreads();

    float uu = d * rstd_sh * ln_w[t] + ln_b[t];
    g_u[i * C_S + t] = uu;
    u_s[t] = uu;
    __syncthreads();

    int z = t & (C_Z - 1);
    int base = (t < C_Z) ? C_S : 0;
    float acc = (t < C_Z) ? b_pair[z] : 0.f;
    #pragma unroll 8
    for (int c = 0; c < C_S; c++)
        acc += u_s[c] * W_pair[(base + c) * C_Z + z];
    if (t < C_Z) g_zjb[i * C_Z + z] = acc;
    else         g_zib[i * C_Z + z] = acc;
}

// ---------------------------------------------------------------------------
// Kernel 2: split W3 into transposed bf16 hi/lo:  g_w3t_*[z*C_S + c]
// ---------------------------------------------------------------------------
__global__ void w3split_kernel(const float* __restrict__ W_pair)
{
    int c = blockIdx.x;             // 0..255
    int z = threadIdx.x;            // 0..127
    float v = W_pair[(2 * C_S + c) * C_Z + z];
    __nv_bfloat16 h = __float2bfloat16(v);
    g_w3t_hi[z * C_S + c] = h;
    g_w3t_lo[z * C_S + c] = __float2bfloat16(v - __bfloat162float(h));
}

// ---------------------------------------------------------------------------
// Kernel 3: mma.sync pair kernel.
// Grid (128, 4): bx = j-group (4 j), by = i-tile (128 rows). 256 threads.
// Warp grid 2(M) x 4(N): warp tile 64 x 32. Per j: D = A'_j @ W3t,
// A'_j[i,c] = u[i,c]*u[j,c] (bf16 hi/lo), W3t fixed in SMEM (hi/lo).
// 3 mma products: Ah*Wh + Ah*Wl + Al*Wh. fp32 accum in registers.
// ---------------------------------------------------------------------------
#define KC 32                         // K chunk (2 k16 steps)
#define NCHUNK (C_S / KC)             // 8

// SMEM layout (bytes)
#define SM_W3H   0                    // [z=128][c=256] bf16 swizzled  65536
#define SM_W3L   65536                //                               65536
#define SM_AP    131072               // 2 bufs x [i=128][128B]        32768
#define SM_ERP   163840               // 66 x 132 f32                  34848
#define SM_ECP   198688               // 4 x 132 f32                    2112
#define SM_ZJB   200800               // 4 x 128 f32                    2048
#define SM_UJ    202848               // 4 x 256 f32                    4096
#define SM_CH    206944               // 128 int                         512
#define SM_RI    207456               // 128 int                         512
#define SMEM_TOTAL 207968

// swizzled W3 smem byte offset for (z, c16) ; c16 = c/8 in [0,32)
__device__ __forceinline__ uint32_t w3_off(int z, int c16) {
    return (uint32_t)(z * 512 + ((c16 & ~7) + ((c16 ^ (z & 7)) & 7)) * 16);
}
// swizzled A' byte offset for (row, chunk) ; chunk in [0,8): 0-3 hi, 4-7 lo
__device__ __forceinline__ uint32_t ap_off(int row, int ch) {
    return (uint32_t)(row * 128 + (ch ^ (row & 7)) * 16);
}

// build A' chunk kcg (cols kcg*32..+31) for column j of the CTA into buf
__device__ __forceinline__ void build_chunk(const char* smem, uint32_t ap_base,
                                            int i0, int jg, int kcg, int t)
{
    const int r = t >> 1, half = t & 1;
    const int c0 = kcg * KC + half * 16;
    const float4* up = (const float4*)(g_u + (size_t)(i0 + r) * C_S + c0);
    const float4* jp = (const float4*)((const float*)(smem + SM_UJ) + jg * C_S + c0);

    uint32_t hi[8], lo[8];
    #pragma unroll
    for (int q = 0; q < 4; q++) {
        float4 u = up[q];
        float4 w = jp[q];
        float p0 = u.x * w.x, p1 = u.y * w.y, p2 = u.z * w.z, p3 = u.w * w.w;
        uint32_t h01 = pack_bf16x2(p1, p0);
        uint32_t h23 = pack_bf16x2(p3, p2);
        float hf0 = __uint_as_float(h01 << 16);
        float hf1 = __uint_as_float(h01 & 0xffff0000u);
        float hf2 = __uint_as_float(h23 << 16);
        float hf3 = __uint_as_float(h23 & 0xffff0000u);
        hi[2 * q]     = h01;
        hi[2 * q + 1] = h23;
        lo[2 * q]     = pack_bf16x2(p1 - hf1, p0 - hf0);
        lo[2 * q + 1] = pack_bf16x2(p3 - hf3, p2 - hf2);
    }
    char* ap = (char*)smem + (ap_base - smem_u32(smem)); // same as smem + SM_AP + buf*16384
    (void)ap;
    // use byte offsets relative to dynamic smem pointer instead:
    char* apc = const_cast<char*>(smem) + (ap_base);
    int ch0 = half * 2;
    *(uint4*)(apc + ap_off(r, ch0))     = make_uint4(hi[0], hi[1], hi[2], hi[3]);
    *(uint4*)(apc + ap_off(r, ch0 + 1)) = make_uint4(hi[4], hi[5], hi[6], hi[7]);
    *(uint4*)(apc + ap_off(r, ch0 + 4)) = make_uint4(lo[0], lo[1], lo[2], lo[3]);
    *(uint4*)(apc + ap_off(r, ch0 + 5)) = make_uint4(lo[4], lo[5], lo[6], lo[7]);
}

__global__ __launch_bounds__(256)
void pair_kernel(const int* __restrict__ chain,
                 const int* __restrict__ ridx,
                 const float* __restrict__ E_cp,
                 const float* __restrict__ E_rp,
                 float* __restrict__ out_z)
{
    extern __shared__ char smem[];
    const uint32_t sbase = smem_u32(smem);
    const int t = threadIdx.x;           // 256
    const int lane = t & 31, wid = t >> 5;
    const int wm = wid >> 2;             // 0..1  (M)
    const int wn = wid & 3;              // 0..3  (N)
    const int j0 = blockIdx.x * 4;
    const int i0 = blockIdx.y * 128;

    float* erp_s = (float*)(smem + SM_ERP);
    float* ecp_s = (float*)(smem + SM_ECP);
    float* zjb_s = (float*)(smem + SM_ZJB);
    float* uj_s  = (float*)(smem + SM_UJ);
    int*   ch_s  = (int*)  (smem + SM_CH);
    int*   ri_s  = (int*)  (smem + SM_RI);

    // ---- prologue: stage W3 (swizzled), tables, uj, chain/ridx ----
    for (int idx = t; idx < 8192; idx += 256) {       // 16B chunks, hi then lo
        int hilo = idx >> 12;
        int rem  = idx & 4095;
        int z    = rem >> 5;
        int c16  = rem & 31;
        const __nv_bfloat16* src = (hilo ? g_w3t_lo : g_w3t_hi) + (size_t)z * C_S + c16 * 8;
        uint4 v = *(const uint4*)src;
        *(uint4*)(smem + (hilo ? SM_W3L : SM_W3H) + w3_off(z, c16)) = v;
    }
    for (int idx = t; idx < 66 * C_Z; idx += 256)
        erp_s[(idx >> 7) * 132 + (idx & 127)] = E_rp[idx];
    for (int idx = t; idx < 4 * C_Z; idx += 256)
        ecp_s[(idx >> 7) * 132 + (idx & 127)] = E_cp[idx];
    for (int idx = t; idx < 4 * C_Z; idx += 256)
        zjb_s[idx] = g_zjb[(j0 + (idx >> 7)) * C_Z + (idx & 127)];
    for (int idx = t; idx < 4 * C_S; idx += 256)
        uj_s[idx] = g_u[(j0 + (idx >> 8)) * C_S + (idx & 255)];
    if (t < 128) { ch_s[t] = chain[i0 + t]; ri_s[t] = ridx[i0 + t]; }

    int cj[4], rj[4];
    #pragma unroll
    for (int jj = 0; jj < 4; jj++) { cj[jj] = chain[j0 + jj]; rj[jj] = ridx[j0 + jj]; }
    __syncthreads();

    // lane address components (ldmatrix)
    const int arow_l = lane & 15;          // A: row within 16
    const int achk_l = lane >> 4;          // A: k-8 half
    const int bgrp   = lane >> 3;
    const int bz_l   = ((bgrp >> 1) << 3) + (lane & 7);   // B: z row within 16
    const int bco    = bgrp & 1;                          // B: k-8 half

    #pragma unroll 1
    for (int jg = 0; jg < 4; jg++) {
        float acc[4][4][4];
        #pragma unroll
        for (int mt = 0; mt < 4; mt++)
            #pragma unroll
            for (int nt = 0; nt < 4; nt++)
                #pragma unroll
                for (int q = 0; q < 4; q++) acc[mt][nt][q] = 0.f;

        build_chunk(smem, SM_AP, i0, jg, 0, t);
        __syncthreads();

        #pragma unroll 1
        for (int kcg = 0; kcg < NCHUNK; kcg++) {
            if (kcg + 1 < NCHUNK)
                build_chunk(smem, SM_AP + ((kcg + 1) & 1) * 16384, i0, jg, kcg + 1, t);

            const uint32_t apb = sbase + SM_AP + (kcg & 1) * 16384;
            #pragma unroll
            for (int kk = 0; kk < 2; kk++) {
                // B fragments (4 n-tiles, hi & lo)
                uint32_t bh[4][2], bl[4][2];
                #pragma unroll
                for (int pair = 0; pair < 2; pair++) {
                    int z  = wn * 32 + pair * 16 + bz_l;
                    int c16 = kcg * 4 + kk * 2 + bco;
                    uint32_t ah_ = sbase + SM_W3H + w3_off(z, c16);
                    uint32_t al_ = sbase + SM_W3L + w3_off(z, c16);
                    ldsm_x4(bh[pair*2][0], bh[pair*2][1], bh[pair*2+1][0], bh[pair*2+1][1], ah_);
                    ldsm_x4(bl[pair*2][0], bl[pair*2][1], bl[pair*2+1][0], bl[pair*2+1][1], al_);
                }
                // A fragments (4 m-tiles, hi & lo)
                uint32_t ahf[4][4], alf[4][4];
                #pragma unroll
                for (int mt = 0; mt < 4; mt++) {
                    int row = wm * 64 + mt * 16 + arow_l;
                    int chh = kk * 2 + achk_l;
                    ldsm_x4(ahf[mt][0], ahf[mt][1], ahf[mt][2], ahf[mt][3],
                            apb + ap_off(row, chh));
                    ldsm_x4(alf[mt][0], alf[mt][1], alf[mt][2], alf[mt][3],
                            apb + ap_off(row, chh + 4));
                }
                #pragma unroll
                for (int mt = 0; mt < 4; mt++)
                    #pragma unroll
                    for (int nt = 0; nt < 4; nt++) {
                        mma16816(acc[mt][nt], ahf[mt], bh[nt]);
                        mma16816(acc[mt][nt], ahf[mt], bl[nt]);
                        mma16816(acc[mt][nt], alf[mt], bh[nt]);
                    }
            }
            __syncthreads();
        }

        // ---- epilogue for this j ----
        const int g = lane >> 2, tig = lane & 3;
        #pragma unroll
        for (int mt = 0; mt < 4; mt++) {
            #pragma unroll
            for (int h = 0; h < 2; h++) {
                int row_l = wm * 64 + mt * 16 + g + h * 8;
                int ci = ch_s[row_l], ri = ri_s[row_l];
                int cp = ci * 2 + cj[jg];
                int dd = ri - rj[jg];
                int dcl = dd < -32 ? -32 : (dd > 32 ? 32 : dd);
                int rp = (ci == cj[jg]) ? (dcl + 32) : 65;
                const float* erow = erp_s + rp * 132;
                const float* crow = ecp_s + cp * 132;
                const float* zjr  = zjb_s + jg * C_Z;
                const float* zir  = g_zib + (size_t)(i0 + row_l) * C_Z;
                float* orow = out_z + ((size_t)(i0 + row_l) * L_RES + (j0 + jg)) * C_Z;
                #pragma unroll
                for (int nt = 0; nt < 4; nt++) {
                    int col = wn * 32 + nt * 8 + tig * 2;
                    float2 zi2 = *(const float2*)(zir + col);
                    float2 zj2 = *(const float2*)(zjr + col);
                    float2 ec2 = *(const float2*)(crow + col);
                    float2 er2 = *(const float2*)(erow + col);
                    float2 o;
                    o.x = acc[mt][nt][h * 2]     + zi2.x + zj2.x + ec2.x + er2.x;
                    o.y = acc[mt][nt][h * 2 + 1] + zi2.y + zj2.y + ec2.y + er2.y;
                    *(float2*)(orow + col) = o;
                }
            }
        }
        __syncthreads();   // protect A' buf0 before next j's first build
    }
}

// ---------------------------------------------------------------------------
extern "C" void kernel_launch(void* const* d_in, const int* in_sizes, int n_in,
                              void* d_out, int out_size)
{
    const int*   seq     = (const int*)  d_in[0];
    const int*   chain   = (const int*)  d_in[1];
    const int*   ridx    = (const int*)  d_in[2];
    const float* E_aa    = (const float*)d_in[3];
    const float* E_pos   = (const float*)d_in[4];
    const float* E_chain = (const float*)d_in[5];
    const float* E_cp    = (const float*)d_in[6];
    const float* E_rp    = (const float*)d_in[7];
    const float* W_pair  = (const float*)d_in[8];
    const float* b_pair  = (const float*)d_in[9];
    const float* ln_w    = (const float*)d_in[10];
    const float* ln_b    = (const float*)d_in[11];

    float* out_s = (float*)d_out;
    float* out_z = out_s + (size_t)L_RES * C_S;

    static int smem_set = 0;
    if (!smem_set) {
        cudaFuncSetAttribute(pair_kernel, cudaFuncAttributeMaxDynamicSharedMemorySize,
                             SMEM_TOTAL);
        smem_set = 1;
    }

    prep_kernel<<<L_RES, C_S>>>(seq, chain, ridx, E_aa, E_pos, E_chain,
                                W_pair, b_pair, ln_w, ln_b, out_s);
    w3split_kernel<<<C_S, C_Z>>>(W_pair);
    pair_kernel<<<dim3(L_RES / 4, 4), 256, SMEM_TOTAL>>>(chain, ridx, E_cp, E_rp, out_z);
}

// round 6
// speedup vs baseline: 1.8068x; 1.2498x over previous
#include <cuda_runtime.h>
#include <cuda_bf16.h>
#include <cuda_fp16.h>
#include <cstdint>

#define L_RES 512
#define C_S   256
#define C_Z   128
#define LN_EPS 1e-5f

// ---------------------------------------------------------------------------
// Device scratch
// ---------------------------------------------------------------------------
__device__ __align__(16) float g_u[L_RES * C_S];        // LayerNorm'd embeddings
__device__ __align__(16) float g_zjb[L_RES * C_Z];      // u @ W2 + b_pair
__device__ __align__(16) float g_zib[L_RES * C_Z];      // u @ W1
__device__ __align__(16) __half g_w3t[C_Z * C_S];       // W3^T fp16  [z][c]

// ---------------------------------------------------------------------------
// Base-PTX tensor helpers (valid on compute_103)
// ---------------------------------------------------------------------------
__device__ __forceinline__ uint32_t smem_u32(const void* p) {
    uint32_t a;
    asm("{ .reg .u64 t; cvta.to.shared.u64 t, %1; cvt.u32.u64 %0, t; }"
        : "=r"(a) : "l"(p));
    return a;
}

__device__ __forceinline__ void ldsm_x4(uint32_t& r0, uint32_t& r1,
                                        uint32_t& r2, uint32_t& r3, uint32_t addr) {
    asm volatile("ldmatrix.sync.aligned.m8n8.x4.shared.b16 {%0,%1,%2,%3}, [%4];"
                 : "=r"(r0), "=r"(r1), "=r"(r2), "=r"(r3) : "r"(addr));
}

__device__ __forceinline__ void mma16816(float* c, const uint32_t* a, const uint32_t* b) {
    asm volatile(
        "mma.sync.aligned.m16n8k16.row.col.f32.f16.f16.f32 "
        "{%0,%1,%2,%3}, {%4,%5,%6,%7}, {%8,%9}, {%0,%1,%2,%3};"
        : "+f"(c[0]), "+f"(c[1]), "+f"(c[2]), "+f"(c[3])
        : "r"(a[0]), "r"(a[1]), "r"(a[2]), "r"(a[3]), "r"(b[0]), "r"(b[1]));
}

// ---------------------------------------------------------------------------
// Kernel 1: gather + LayerNorm + zjb (u@W2 + b) + zib (u@W1)
// ---------------------------------------------------------------------------
__global__ void prep_kernel(const int* __restrict__ seq,
                            const int* __restrict__ chain,
                            const int* __restrict__ ridx,
                            const float* __restrict__ E_aa,
                            const float* __restrict__ E_pos,
                            const float* __restrict__ E_chain,
                            const float* __restrict__ W_pair,
                            const float* __restrict__ b_pair,
                            const float* __restrict__ ln_w,
                            const float* __restrict__ ln_b,
                            float* __restrict__ out_s)
{
    int i = blockIdx.x;
    int t = threadIdx.x;            // 256 threads == C_S

    __shared__ float u_s[C_S];
    __shared__ float red[8];
    __shared__ float mu_sh, rstd_sh;

    int sq = seq[i], ci = chain[i], ri = ridx[i];
    float v = E_aa[sq * C_S + t] + E_pos[ri * C_S + t] + E_chain[ci * C_S + t];
    out_s[i * C_S + t] = v;

    float x = v;
    #pragma unroll
    for (int o = 16; o; o >>= 1) x += __shfl_xor_sync(0xffffffffu, x, o);
    if ((t & 31) == 0) red[t >> 5] = x;
    __syncthreads();
    if (t == 0) {
        float s = 0.f;
        #pragma unroll
        for (int w = 0; w < 8; w++) s += red[w];
        mu_sh = s * (1.f / C_S);
    }
    __syncthreads();
    float mu = mu_sh;
    float d  = v - mu;

    x = d * d;
    #pragma unroll
    for (int o = 16; o; o >>= 1) x += __shfl_xor_sync(0xffffffffu, x, o);
    if ((t & 31) == 0) red[t >> 5] = x;
    __syncthreads();
    if (t == 0) {
        float s = 0.f;
        #pragma unroll
        for (int w = 0; w < 8; w++) s += red[w];
        rstd_sh = rsqrtf(s * (1.f / C_S) + LN_EPS);
    }
    __syncthreads();

    float uu = d * rstd_sh * ln_w[t] + ln_b[t];
    g_u[i * C_S + t] = uu;
    u_s[t] = uu;
    __syncthreads();

    // 4 independent accumulator chains (MLP=4)
    int z = t & (C_Z - 1);
    int base = (t < C_Z) ? C_S : 0;
    const float* Wz = W_pair + (size_t)base * C_Z + z;
    float a0 = 0.f, a1 = 0.f, a2 = 0.f, a3 = 0.f;
    #pragma unroll 4
    for (int c = 0; c < C_S; c += 4) {
        a0 += u_s[c + 0] * Wz[(c + 0) * C_Z];
        a1 += u_s[c + 1] * Wz[(c + 1) * C_Z];
        a2 += u_s[c + 2] * Wz[(c + 2) * C_Z];
        a3 += u_s[c + 3] * Wz[(c + 3) * C_Z];
    }
    float acc = (a0 + a1) + (a2 + a3);
    if (t < C_Z) g_zjb[i * C_Z + z] = acc + b_pair[z];
    else         g_zib[i * C_Z + z] = acc;
}

// ---------------------------------------------------------------------------
// Kernel 2: W3 -> transposed fp16:  g_w3t[z*C_S + c]
// ---------------------------------------------------------------------------
__global__ void w3split_kernel(const float* __restrict__ W_pair)
{
    int c = blockIdx.x;             // 0..255
    int z = threadIdx.x;            // 0..127
    g_w3t[z * C_S + c] = __float2half_rn(W_pair[(2 * C_S + c) * C_Z + z]);
}

// ---------------------------------------------------------------------------
// Kernel 3: mma.sync fp16 pair kernel.
// Grid (128, 4): bx = j-group (4 j), by = i-tile (128 rows). 256 threads.
// Warp grid 2(M) x 4(N): warp tile 64 x 32. Per j: D = A'_j @ W3t,
// A'_j[i,c] = u[i,c]*u[j,c] split fp16 hi/lo; W3t single fp16 in SMEM.
// 2 products: Ah*W + Al*W. fp32 accum in registers.
// ---------------------------------------------------------------------------
#define NCHUNK 8                      // K chunks of 32

// SMEM layout (bytes)
#define SM_W3H   0                    // [z=128][c=256] fp16 swizzled  65536
#define SM_AP    65536                // 2 bufs x [i=128][128B]        32768
#define SM_ERP   98304                // 66 x 132 f32                  34848
#define SM_ECP   133152               // 4 x 132 f32                    2112
#define SM_ZJB   135264               // 4 x 128 f32                    2048
#define SM_UJ    137312               // 4 x 256 f32                    4096
#define SM_CH    141408               // 128 int                         512
#define SM_RI    141920               // 128 int                         512
#define SMEM_TOTAL 142432

// swizzled W3 smem byte offset for (z, c16) ; c16 = c/8 in [0,32)
__device__ __forceinline__ uint32_t w3_off(int z, int c16) {
    return (uint32_t)(z * 512 + ((c16 & ~7) + ((c16 ^ (z & 7)) & 7)) * 16);
}
// swizzled A' byte offset for (row, chunk) ; chunk in [0,8): 0-3 hi, 4-7 lo
__device__ __forceinline__ uint32_t ap_off(int row, int ch) {
    return (uint32_t)(row * 128 + (ch ^ (row & 7)) * 16);
}

__device__ __forceinline__ void load_u(float4* ur, int i0, int kcg, int t) {
    const int r = t >> 1, half = t & 1;
    const float4* up = (const float4*)(g_u + (size_t)(i0 + r) * C_S + kcg * 32 + half * 16);
    ur[0] = up[0]; ur[1] = up[1]; ur[2] = up[2]; ur[3] = up[3];
}

__device__ __forceinline__ void pack_store(char* smem, int buf, const float4* ur,
                                           int jg, int kcg, int t)
{
    const int r = t >> 1, half = t & 1;
    const int c0 = kcg * 32 + half * 16;
    const float4* jp = (const float4*)((const float*)(smem + SM_UJ) + jg * C_S + c0);

    uint32_t hi[8], lo[8];
    #pragma unroll
    for (int q = 0; q < 4; q++) {
        float4 u = ur[q];
        float4 w = jp[q];
        float p0 = u.x * w.x, p1 = u.y * w.y, p2 = u.z * w.z, p3 = u.w * w.w;
        __half2 h01 = __floats2half2_rn(p0, p1);
        __half2 h23 = __floats2half2_rn(p2, p3);
        float2 f01 = __half22float2(h01);
        float2 f23 = __half22float2(h23);
        __half2 l01 = __floats2half2_rn(p0 - f01.x, p1 - f01.y);
        __half2 l23 = __floats2half2_rn(p2 - f23.x, p3 - f23.y);
        hi[2 * q]     = *reinterpret_cast<uint32_t*>(&h01);
        hi[2 * q + 1] = *reinterpret_cast<uint32_t*>(&h23);
        lo[2 * q]     = *reinterpret_cast<uint32_t*>(&l01);
        lo[2 * q + 1] = *reinterpret_cast<uint32_t*>(&l23);
    }
    char* apc = smem + SM_AP + buf * 16384;
    int ch0 = half * 2;
    *(uint4*)(apc + ap_off(r, ch0))     = make_uint4(hi[0], hi[1], hi[2], hi[3]);
    *(uint4*)(apc + ap_off(r, ch0 + 1)) = make_uint4(hi[4], hi[5], hi[6], hi[7]);
    *(uint4*)(apc + ap_off(r, ch0 + 4)) = make_uint4(lo[0], lo[1], lo[2], lo[3]);
    *(uint4*)(apc + ap_off(r, ch0 + 5)) = make_uint4(lo[4], lo[5], lo[6], lo[7]);
}

__global__ __launch_bounds__(256)
void pair_kernel(const int* __restrict__ chain,
                 const int* __restrict__ ridx,
                 const float* __restrict__ E_cp,
                 const float* __restrict__ E_rp,
                 float* __restrict__ out_z)
{
    extern __shared__ char smem[];
    const uint32_t sbase = smem_u32(smem);
    const int t = threadIdx.x;           // 256
    const int lane = t & 31, wid = t >> 5;
    const int wm = wid >> 2;             // 0..1  (M)
    const int wn = wid & 3;              // 0..3  (N)
    const int j0 = blockIdx.x * 4;
    const int i0 = blockIdx.y * 128;

    float* erp_s = (float*)(smem + SM_ERP);
    float* ecp_s = (float*)(smem + SM_ECP);
    float* zjb_s = (float*)(smem + SM_ZJB);
    float* uj_s  = (float*)(smem + SM_UJ);
    int*   ch_s  = (int*)  (smem + SM_CH);
    int*   ri_s  = (int*)  (smem + SM_RI);

    // ---- prologue: stage W3 (swizzled), tables, uj, chain/ridx ----
    for (int idx = t; idx < 4096; idx += 256) {       // 16B chunks
        int z = idx >> 5, c16 = idx & 31;
        uint4 v = *(const uint4*)(g_w3t + (size_t)z * C_S + c16 * 8);
        *(uint4*)(smem + SM_W3H + w3_off(z, c16)) = v;
    }
    for (int idx = t; idx < 66 * C_Z; idx += 256)
        erp_s[(idx >> 7) * 132 + (idx & 127)] = E_rp[idx];
    for (int idx = t; idx < 4 * C_Z; idx += 256)
        ecp_s[(idx >> 7) * 132 + (idx & 127)] = E_cp[idx];
    for (int idx = t; idx < 4 * C_Z; idx += 256)
        zjb_s[idx] = g_zjb[(j0 + (idx >> 7)) * C_Z + (idx & 127)];
    for (int idx = t; idx < 4 * C_S; idx += 256)
        uj_s[idx] = g_u[(j0 + (idx >> 8)) * C_S + (idx & 255)];
    if (t < 128) { ch_s[t] = chain[i0 + t]; ri_s[t] = ridx[i0 + t]; }

    int cj[4], rj[4];
    #pragma unroll
    for (int jj = 0; jj < 4; jj++) { cj[jj] = chain[j0 + jj]; rj[jj] = ridx[j0 + jj]; }
    __syncthreads();

    // lane address components (ldmatrix)
    const int arow_l = lane & 15;          // A: row within 16
    const int achk_l = lane >> 4;          // A: k-8 half
    const int bgrp   = lane >> 3;
    const int bz_l   = ((bgrp >> 1) << 3) + (lane & 7);   // B: z row within 16
    const int bco    = bgrp & 1;                          // B: k-8 half

    float4 ur[4];
    load_u(ur, i0, 0, t);                 // prefetch chunk 0

    #pragma unroll 1
    for (int jg = 0; jg < 4; jg++) {
        float acc[4][4][4];
        #pragma unroll
        for (int mt = 0; mt < 4; mt++)
            #pragma unroll
            for (int nt = 0; nt < 4; nt++)
                #pragma unroll
                for (int q = 0; q < 4; q++) acc[mt][nt][q] = 0.f;

        #pragma unroll 1
        for (int kcg = 0; kcg < NCHUNK; kcg++) {
            pack_store(smem, kcg & 1, ur, jg, kcg, t);
            __syncthreads();
            // prefetch next chunk's u rows (chunk 0 again at kcg==7, for next jg)
            load_u(ur, i0, (kcg < NCHUNK - 1) ? kcg + 1 : 0, t);

            const uint32_t apb = sbase + SM_AP + (kcg & 1) * 16384;
            #pragma unroll
            for (int kk = 0; kk < 2; kk++) {
                // B fragments (4 n-tiles)
                uint32_t bh[4][2];
                #pragma unroll
                for (int pair = 0; pair < 2; pair++) {
                    int z   = wn * 32 + pair * 16 + bz_l;
                    int c16 = kcg * 4 + kk * 2 + bco;
                    uint32_t ad = sbase + SM_W3H + w3_off(z, c16);
                    ldsm_x4(bh[pair*2][0], bh[pair*2][1], bh[pair*2+1][0], bh[pair*2+1][1], ad);
                }
                // A fragments (4 m-tiles, hi & lo)
                uint32_t ahf[4][4], alf[4][4];
                #pragma unroll
                for (int mt = 0; mt < 4; mt++) {
                    int row = wm * 64 + mt * 16 + arow_l;
                    int chh = kk * 2 + achk_l;
                    ldsm_x4(ahf[mt][0], ahf[mt][1], ahf[mt][2], ahf[mt][3],
                            apb + ap_off(row, chh));
                    ldsm_x4(alf[mt][0], alf[mt][1], alf[mt][2], alf[mt][3],
                            apb + ap_off(row, chh + 4));
                }
                // all hi products first, then all lo: RAW distance = 16
                #pragma unroll
                for (int mt = 0; mt < 4; mt++)
                    #pragma unroll
                    for (int nt = 0; nt < 4; nt++)
                        mma16816(acc[mt][nt], ahf[mt], bh[nt]);
                #pragma unroll
                for (int mt = 0; mt < 4; mt++)
                    #pragma unroll
                    for (int nt = 0; nt < 4; nt++)
                        mma16816(acc[mt][nt], alf[mt], bh[nt]);
            }
        }

        // ---- epilogue for this j ----
        const int g = lane >> 2, tig = lane & 3;
        #pragma unroll
        for (int mt = 0; mt < 4; mt++) {
            #pragma unroll
            for (int h = 0; h < 2; h++) {
                int row_l = wm * 64 + mt * 16 + g + h * 8;
                int ci = ch_s[row_l], ri = ri_s[row_l];
                int cp = ci * 2 + cj[jg];
                int dd = ri - rj[jg];
                int dcl = dd < -32 ? -32 : (dd > 32 ? 32 : dd);
                int rp = (ci == cj[jg]) ? (dcl + 32) : 65;
                const float* erow = erp_s + rp * 132;
                const float* crow = ecp_s + cp * 132;
                const float* zjr  = zjb_s + jg * C_Z;
                const float* zir  = g_zib + (size_t)(i0 + row_l) * C_Z;
                float* orow = out_z + ((size_t)(i0 + row_l) * L_RES + (j0 + jg)) * C_Z;
                #pragma unroll
                for (int nt = 0; nt < 4; nt++) {
                    int col = wn * 32 + nt * 8 + tig * 2;
                    float2 zi2 = *(const float2*)(zir + col);
                    float2 zj2 = *(const float2*)(zjr + col);
                    float2 ec2 = *(const float2*)(crow + col);
                    float2 er2 = *(const float2*)(erow + col);
                    float2 o;
                    o.x = acc[mt][nt][h * 2]     + zi2.x + zj2.x + ec2.x + er2.x;
                    o.y = acc[mt][nt][h * 2 + 1] + zi2.y + zj2.y + ec2.y + er2.y;
                    *(float2*)(orow + col) = o;
                }
            }
        }
        // no extra bar needed: per-chunk bars separate buffer reuse across jg
    }
}

// ---------------------------------------------------------------------------
extern "C" void kernel_launch(void* const* d_in, const int* in_sizes, int n_in,
                              void* d_out, int out_size)
{
    const int*   seq     = (const int*)  d_in[0];
    const int*   chain   = (const int*)  d_in[1];
    const int*   ridx    = (const int*)  d_in[2];
    const float* E_aa    = (const float*)d_in[3];
    const float* E_pos   = (const float*)d_in[4];
    const float* E_chain = (const float*)d_in[5];
    const float* E_cp    = (const float*)d_in[6];
    const float* E_rp    = (const float*)d_in[7];
    const float* W_pair  = (const float*)d_in[8];
    const float* b_pair  = (const float*)d_in[9];
    const float* ln_w    = (const float*)d_in[10];
    const float* ln_b    = (const float*)d_in[11];

    float* out_s = (float*)d_out;
    float* out_z = out_s + (size_t)L_RES * C_S;

    static int smem_set = 0;
    if (!smem_set) {
        cudaFuncSetAttribute(pair_kernel, cudaFuncAttributeMaxDynamicSharedMemorySize,
                             SMEM_TOTAL);
        smem_set = 1;
    }

    prep_kernel<<<L_RES, C_S>>>(seq, chain, ridx, E_aa, E_pos, E_chain,
                                W_pair, b_pair, ln_w, ln_b, out_s);
    w3split_kernel<<<C_S, C_Z>>>(W_pair);
    pair_kernel<<<dim3(L_RES / 4, 4), 256, SMEM_TOTAL>>>(chain, ridx, E_cp, E_rp, out_z);
}

// round 7
// speedup vs baseline: 2.5746x; 1.4249x over previous
#include <cuda_runtime.h>
#include <cuda_bf16.h>
#include <cuda_fp16.h>
#include <cstdint>

#define L_RES 512
#define C_S   256
#define C_Z   128
#define LN_EPS 1e-5f

// ---------------------------------------------------------------------------
// Device scratch
// ---------------------------------------------------------------------------
__device__ __align__(16) float g_u[L_RES * C_S];        // LayerNorm'd embeddings
__device__ __align__(16) float g_zjb[L_RES * C_Z];      // u @ W2 + b_pair
__device__ __align__(16) float g_zib[L_RES * C_Z];      // u @ W1
__device__ __align__(16) __half g_w3t[C_Z * C_S];       // W3^T fp16  [z][c]

// ---------------------------------------------------------------------------
// Base-PTX tensor helpers (valid on compute_103)
// ---------------------------------------------------------------------------
__device__ __forceinline__ uint32_t smem_u32(const void* p) {
    uint32_t a;
    asm("{ .reg .u64 t; cvta.to.shared.u64 t, %1; cvt.u32.u64 %0, t; }"
        : "=r"(a) : "l"(p));
    return a;
}

__device__ __forceinline__ void ldsm_x4(uint32_t& r0, uint32_t& r1,
                                        uint32_t& r2, uint32_t& r3, uint32_t addr) {
    asm volatile("ldmatrix.sync.aligned.m8n8.x4.shared.b16 {%0,%1,%2,%3}, [%4];"
                 : "=r"(r0), "=r"(r1), "=r"(r2), "=r"(r3) : "r"(addr));
}

__device__ __forceinline__ void mma16816(float* c, const uint32_t* a, const uint32_t* b) {
    asm volatile(
        "mma.sync.aligned.m16n8k16.row.col.f32.f16.f16.f32 "
        "{%0,%1,%2,%3}, {%4,%5,%6,%7}, {%8,%9}, {%0,%1,%2,%3};"
        : "+f"(c[0]), "+f"(c[1]), "+f"(c[2]), "+f"(c[3])
        : "r"(a[0]), "r"(a[1]), "r"(a[2]), "r"(a[3]), "r"(b[0]), "r"(b[1]));
}

// ---------------------------------------------------------------------------
// Kernel 1: gather + LayerNorm + zjb (u@W2 + b) + zib (u@W1)
// ---------------------------------------------------------------------------
__global__ void prep_kernel(const int* __restrict__ seq,
                            const int* __restrict__ chain,
                            const int* __restrict__ ridx,
                            const float* __restrict__ E_aa,
                            const float* __restrict__ E_pos,
                            const float* __restrict__ E_chain,
                            const float* __restrict__ W_pair,
                            const float* __restrict__ b_pair,
                            const float* __restrict__ ln_w,
                            const float* __restrict__ ln_b,
                            float* __restrict__ out_s)
{
    int i = blockIdx.x;
    int t = threadIdx.x;            // 256 threads == C_S

    __shared__ float u_s[C_S];
    __shared__ float red[8];
    __shared__ float mu_sh, rstd_sh;

    int sq = seq[i], ci = chain[i], ri = ridx[i];
    float v = E_aa[sq * C_S + t] + E_pos[ri * C_S + t] + E_chain[ci * C_S + t];
    out_s[i * C_S + t] = v;

    float x = v;
    #pragma unroll
    for (int o = 16; o; o >>= 1) x += __shfl_xor_sync(0xffffffffu, x, o);
    if ((t & 31) == 0) red[t >> 5] = x;
    __syncthreads();
    if (t == 0) {
        float s = 0.f;
        #pragma unroll
        for (int w = 0; w < 8; w++) s += red[w];
        mu_sh = s * (1.f / C_S);
    }
    __syncthreads();
    float mu = mu_sh;
    float d  = v - mu;

    x = d * d;
    #pragma unroll
    for (int o = 16; o; o >>= 1) x += __shfl_xor_sync(0xffffffffu, x, o);
    if ((t & 31) == 0) red[t >> 5] = x;
    __syncthreads();
    if (t == 0) {
        float s = 0.f;
        #pragma unroll
        for (int w = 0; w < 8; w++) s += red[w];
        rstd_sh = rsqrtf(s * (1.f / C_S) + LN_EPS);
    }
    __syncthreads();

    float uu = d * rstd_sh * ln_w[t] + ln_b[t];
    g_u[i * C_S + t] = uu;
    u_s[t] = uu;
    __syncthreads();

    // 8 independent accumulator chains (MLP=8)
    int z = t & (C_Z - 1);
    int base = (t < C_Z) ? C_S : 0;
    const float* Wz = W_pair + (size_t)base * C_Z + z;
    float a[8];
    #pragma unroll
    for (int q = 0; q < 8; q++) a[q] = 0.f;
    #pragma unroll 2
    for (int c = 0; c < C_S; c += 8) {
        #pragma unroll
        for (int q = 0; q < 8; q++)
            a[q] += u_s[c + q] * Wz[(c + q) * C_Z];
    }
    float acc = ((a[0] + a[1]) + (a[2] + a[3])) + ((a[4] + a[5]) + (a[6] + a[7]));
    if (t < C_Z) g_zjb[i * C_Z + z] = acc + b_pair[z];
    else         g_zib[i * C_Z + z] = acc;
}

// ---------------------------------------------------------------------------
// Kernel 2: W3 -> transposed fp16:  g_w3t[z*C_S + c]
// ---------------------------------------------------------------------------
__global__ void w3split_kernel(const float* __restrict__ W_pair)
{
    int c = blockIdx.x;             // 0..255
    int z = threadIdx.x;            // 0..127
    g_w3t[z * C_S + c] = __float2half_rn(W_pair[(2 * C_S + c) * C_Z + z]);
}

// ---------------------------------------------------------------------------
// Kernel 3: mma.sync fp16 pair kernel, single product.
// Grid (128, 4): bx = j-group (4 j), by = i-tile (128 rows). 256 threads.
// Warp grid 2(M) x 4(N): warp tile 64 x 32. Per j: D = A'_j @ W3t,
// A'_j[i,c] = fp16(u[i,c]*u[j,c]); W3t fp16 in SMEM. fp32 accum.
// 2 CTAs/SM (smem 105KB): E_relpos read from L2 in the epilogue.
// ---------------------------------------------------------------------------
#define NCHUNK 8                      // K chunks of 32

// SMEM layout (bytes)
#define SM_W3H   0                    // [z=128][c=256] fp16 swizzled  65536
#define SM_AP    65536                // 2 bufs x [i=128][128B]        32768
#define SM_ECP   98304                // 4 x 132 f32                    2112
#define SM_ZJB   100416               // 4 x 128 f32                    2048
#define SM_UJ    102464               // 4 x 256 f32                    4096
#define SM_CH    106560               // 128 int                         512
#define SM_RI    107072               // 128 int                         512
#define SMEM_TOTAL 107584

// swizzled W3 smem byte offset for (z, c16) ; c16 = c/8 in [0,32)
__device__ __forceinline__ uint32_t w3_off(int z, int c16) {
    return (uint32_t)(z * 512 + ((c16 & ~7) + ((c16 ^ (z & 7)) & 7)) * 16);
}
// swizzled A' byte offset for (row, chunk) ; chunk in [0,4) (hi only)
__device__ __forceinline__ uint32_t ap_off(int row, int ch) {
    return (uint32_t)(row * 128 + (ch ^ (row & 7)) * 16);
}

__device__ __forceinline__ void load_u(float4* ur, int i0, int kcg, int t) {
    const int r = t >> 1, half = t & 1;
    const float4* up = (const float4*)(g_u + (size_t)(i0 + r) * C_S + kcg * 32 + half * 16);
    ur[0] = up[0]; ur[1] = up[1]; ur[2] = up[2]; ur[3] = up[3];
}

__device__ __forceinline__ void pack_store(char* smem, int buf, const float4* ur,
                                           int jg, int kcg, int t)
{
    const int r = t >> 1, half = t & 1;
    const int c0 = kcg * 32 + half * 16;
    const float4* jp = (const float4*)((const float*)(smem + SM_UJ) + jg * C_S + c0);

    uint32_t hi[8];
    #pragma unroll
    for (int q = 0; q < 4; q++) {
        float4 u = ur[q];
        float4 w = jp[q];
        __half2 h01 = __floats2half2_rn(u.x * w.x, u.y * w.y);
        __half2 h23 = __floats2half2_rn(u.z * w.z, u.w * w.w);
        hi[2 * q]     = *reinterpret_cast<uint32_t*>(&h01);
        hi[2 * q + 1] = *reinterpret_cast<uint32_t*>(&h23);
    }
    char* apc = smem + SM_AP + buf * 16384;
    int ch0 = half * 2;
    *(uint4*)(apc + ap_off(r, ch0))     = make_uint4(hi[0], hi[1], hi[2], hi[3]);
    *(uint4*)(apc + ap_off(r, ch0 + 1)) = make_uint4(hi[4], hi[5], hi[6], hi[7]);
}

__global__ __launch_bounds__(256, 2)
void pair_kernel(const int* __restrict__ chain,
                 const int* __restrict__ ridx,
                 const float* __restrict__ E_cp,
                 const float* __restrict__ E_rp,
                 float* __restrict__ out_z)
{
    extern __shared__ char smem[];
    const uint32_t sbase = smem_u32(smem);
    const int t = threadIdx.x;           // 256
    const int lane = t & 31, wid = t >> 5;
    const int wm = wid >> 2;             // 0..1  (M)
    const int wn = wid & 3;              // 0..3  (N)
    const int j0 = blockIdx.x * 4;
    const int i0 = blockIdx.y * 128;

    float* ecp_s = (float*)(smem + SM_ECP);
    float* zjb_s = (float*)(smem + SM_ZJB);
    float* uj_s  = (float*)(smem + SM_UJ);
    int*   ch_s  = (int*)  (smem + SM_CH);
    int*   ri_s  = (int*)  (smem + SM_RI);

    // ---- prologue: stage W3 (swizzled), ecp, zjb, uj, chain/ridx ----
    for (int idx = t; idx < 4096; idx += 256) {       // 16B chunks
        int z = idx >> 5, c16 = idx & 31;
        uint4 v = *(const uint4*)(g_w3t + (size_t)z * C_S + c16 * 8);
        *(uint4*)(smem + SM_W3H + w3_off(z, c16)) = v;
    }
    for (int idx = t; idx < 4 * C_Z; idx += 256)
        ecp_s[(idx >> 7) * 132 + (idx & 127)] = E_cp[idx];
    for (int idx = t; idx < 4 * C_Z; idx += 256)
        zjb_s[idx] = g_zjb[(j0 + (idx >> 7)) * C_Z + (idx & 127)];
    for (int idx = t; idx < 4 * C_S; idx += 256)
        uj_s[idx] = g_u[(j0 + (idx >> 8)) * C_S + (idx & 255)];
    if (t < 128) { ch_s[t] = chain[i0 + t]; ri_s[t] = ridx[i0 + t]; }

    int cj[4], rj[4];
    #pragma unroll
    for (int jj = 0; jj < 4; jj++) { cj[jj] = chain[j0 + jj]; rj[jj] = ridx[j0 + jj]; }
    __syncthreads();

    // lane address components (ldmatrix)
    const int arow_l = lane & 15;          // A: row within 16
    const int achk_l = lane >> 4;          // A: k-8 half
    const int bgrp   = lane >> 3;
    const int bz_l   = ((bgrp >> 1) << 3) + (lane & 7);   // B: z row within 16
    const int bco    = bgrp & 1;                          // B: k-8 half

    float4 ur[4];
    load_u(ur, i0, 0, t);                 // prefetch chunk 0

    #pragma unroll 1
    for (int jg = 0; jg < 4; jg++) {
        float acc[4][4][4];
        #pragma unroll
        for (int mt = 0; mt < 4; mt++)
            #pragma unroll
            for (int nt = 0; nt < 4; nt++)
                #pragma unroll
                for (int q = 0; q < 4; q++) acc[mt][nt][q] = 0.f;

        #pragma unroll 1
        for (int kcg = 0; kcg < NCHUNK; kcg++) {
            pack_store(smem, kcg & 1, ur, jg, kcg, t);
            __syncthreads();
            // prefetch next chunk's u rows (chunk 0 again at kcg==7, for next jg)
            load_u(ur, i0, (kcg < NCHUNK - 1) ? kcg + 1 : 0, t);

            const uint32_t apb = sbase + SM_AP + (kcg & 1) * 16384;
            #pragma unroll
            for (int kk = 0; kk < 2; kk++) {
                // B fragments (4 n-tiles)
                uint32_t bh[4][2];
                #pragma unroll
                for (int pair = 0; pair < 2; pair++) {
                    int z   = wn * 32 + pair * 16 + bz_l;
                    int c16 = kcg * 4 + kk * 2 + bco;
                    uint32_t ad = sbase + SM_W3H + w3_off(z, c16);
                    ldsm_x4(bh[pair*2][0], bh[pair*2][1], bh[pair*2+1][0], bh[pair*2+1][1], ad);
                }
                // A fragments (4 m-tiles)
                uint32_t ahf[4][4];
                #pragma unroll
                for (int mt = 0; mt < 4; mt++) {
                    int row = wm * 64 + mt * 16 + arow_l;
                    int chh = kk * 2 + achk_l;
                    ldsm_x4(ahf[mt][0], ahf[mt][1], ahf[mt][2], ahf[mt][3],
                            apb + ap_off(row, chh));
                }
                #pragma unroll
                for (int mt = 0; mt < 4; mt++)
                    #pragma unroll
                    for (int nt = 0; nt < 4; nt++)
                        mma16816(acc[mt][nt], ahf[mt], bh[nt]);
            }
        }

        // ---- epilogue for this j (E_relpos straight from L2) ----
        const int g = lane >> 2, tig = lane & 3;
        #pragma unroll
        for (int mt = 0; mt < 4; mt++) {
            #pragma unroll
            for (int h = 0; h < 2; h++) {
                int row_l = wm * 64 + mt * 16 + g + h * 8;
                int ci = ch_s[row_l], ri = ri_s[row_l];
                int cp = ci * 2 + cj[jg];
                int dd = ri - rj[jg];
                int dcl = dd < -32 ? -32 : (dd > 32 ? 32 : dd);
                int rp = (ci == cj[jg]) ? (dcl + 32) : 65;
                const float* erow = E_rp + (size_t)rp * C_Z;
                const float* crow = ecp_s + cp * 132;
                const float* zjr  = zjb_s + jg * C_Z;
                const float* zir  = g_zib + (size_t)(i0 + row_l) * C_Z;
                float* orow = out_z + ((size_t)(i0 + row_l) * L_RES + (j0 + jg)) * C_Z;
                #pragma unroll
                for (int nt = 0; nt < 4; nt++) {
                    int col = wn * 32 + nt * 8 + tig * 2;
                    float2 zi2 = *(const float2*)(zir + col);
                    float2 zj2 = *(const float2*)(zjr + col);
                    float2 ec2 = *(const float2*)(crow + col);
                    float2 er2 = *(const float2*)(erow + col);
                    float2 o;
                    o.x = acc[mt][nt][h * 2]     + zi2.x + zj2.x + ec2.x + er2.x;
                    o.y = acc[mt][nt][h * 2 + 1] + zi2.y + zj2.y + ec2.y + er2.y;
                    *(float2*)(orow + col) = o;
                }
            }
        }
        // per-chunk bars separate buffer reuse across jg
    }
}

// ---------------------------------------------------------------------------
extern "C" void kernel_launch(void* const* d_in, const int* in_sizes, int n_in,
                              void* d_out, int out_size)
{
    const int*   seq     = (const int*)  d_in[0];
    const int*   chain   = (const int*)  d_in[1];
    const int*   ridx    = (const int*)  d_in[2];
    const float* E_aa    = (const float*)d_in[3];
    const float* E_pos   = (const float*)d_in[4];
    const float* E_chain = (const float*)d_in[5];
    const float* E_cp    = (const float*)d_in[6];
    const float* E_rp    = (const float*)d_in[7];
    const float* W_pair  = (const float*)d_in[8];
    const float* b_pair  = (const float*)d_in[9];
    const float* ln_w    = (const float*)d_in[10];
    const float* ln_b    = (const float*)d_in[11];

    float* out_s = (float*)d_out;
    float* out_z = out_s + (size_t)L_RES * C_S;

    static int smem_set = 0;
    if (!smem_set) {
        cudaFuncSetAttribute(pair_kernel, cudaFuncAttributeMaxDynamicSharedMemorySize,
                             SMEM_TOTAL);
        smem_set = 1;
    }

    prep_kernel<<<L_RES, C_S>>>(seq, chain, ridx, E_aa, E_pos, E_chain,
                                W_pair, b_pair, ln_w, ln_b, out_s);
    w3split_kernel<<<C_S, C_Z>>>(W_pair);
    pair_kernel<<<dim3(L_RES / 4, 4), 256, SMEM_TOTAL>>>(chain, ridx, E_cp, E_rp, out_z);
}